// round 4
// baseline (speedup 1.0000x reference)
#include <cuda_runtime.h>
#include <math.h>

// LinearAttention: out = tril(rope(Q) @ rope(K)^T) @ V
// Chunked linear-attention formulation:
//   pass0: trig table  g_trig[t][j] = (cos, sin)(t * invf_j)      (1024 CTAs)
//   pass1: per-chunk KV state  S_c = Kr_c^T @ V_c                 (B*NC CTAs)
//   pass2: exclusive prefix    M_c = sum_{j<c} S_j                (B*16 CTAs)
//   pass3: out_c = masked(Qr_c Kr_c^T) V_c + Qr_c @ M_c          (B*NC CTAs)
// All GEMMs: fp32 SIMT with packed fma.rn.f32x2 (SASS FFMA2).
// R2: warp-uniform triangular skip in pass-3 stage B; stage-A skip for chunk 0.
// R3: RoPE trig hoisted into a 2MB L2-resident table (6M sincos -> 262K).

#define BB 8
#define SS 4096
#define DD 128
#define CC 128
#define NC 32          // SS / CC
#define QSTR 132       // padded smem row stride (floats), 16B-aligned
#define ESTR 36        // E-tile smem stride

// Scratch (no cudaMalloc allowed).
__device__ float4 g_kv4 [(size_t)BB * NC * DD * DD / 4];
__device__ float4 g_pre4[(size_t)BB * NC * DD * DD / 4];
__device__ float2 g_trig[(size_t)SS * 64];            // 2 MB: (cos, sin) per (t, j)

union U2 { unsigned long long u; float2 f; };

__device__ __forceinline__ void ffma2(unsigned long long &d,
                                      unsigned long long a,
                                      unsigned long long b) {
    asm("fma.rn.f32x2 %0, %1, %2, %0;" : "+l"(d) : "l"(a), "l"(b));
}

__device__ __forceinline__ unsigned long long bcast2(float x) {
    U2 u; u.f = make_float2(x, x); return u.u;
}

// Copy nrows*128 floats (row-major, 128/row) from gmem into smem w/ stride QSTR.
__device__ __forceinline__ void load_tile(float* sdst, const float* __restrict__ gsrc,
                                          int nrows, int tid) {
    int total = nrows * 32;                       // float4 count
    for (int g = tid; g < total; g += 256) {
        int row = g >> 5, c4 = g & 31;
        *(float4*)(sdst + row * QSTR + c4 * 4) = ((const float4*)gsrc)[g];
    }
}

// Accurate sin/cos for |ang| up to ~4100 rad, robust under --use_fast_math.
// Cody-Waite: PI2_HI = 6.28125 (8-bit mantissa), k <= ~700 (10 bits) so
// fmaf(-k, PI2_HI, ang) is exact; residual error ~7e-8 rad.
__device__ __forceinline__ void sincos_safe(float ang, float* sn, float* cs) {
    float k = rintf(ang * 0.15915494309189535f);     // ang / (2*pi)
    float r = fmaf(-k, 6.28125f, ang);               // exact
    r = fmaf(-k, 1.9353071795864769e-3f, r);         // 2*pi - 6.28125
    sincosf(r, sn, cs);                              // |r| <= pi: accurate even as __sincosf
}

// In-place RoPE on an [nrows x 128] smem tile (stride QSTR) from the trig table.
__device__ __forceinline__ void rope_tile(float* sx, int nrows, int srow0, int tid) {
    int total = nrows * 64;
    for (int p = tid; p < total; p += 256) {
        int t = p >> 6, j = p & 63;
        float2 cssn = g_trig[(size_t)(srow0 + t) * 64 + j];
        float* r = sx + t * QSTR;
        float x1 = r[j], x2 = r[j + 64];
        r[j]      = x1 * cssn.x - x2 * cssn.y;
        r[j + 64] = x2 * cssn.x + x1 * cssn.y;
    }
}

// GEMM variant C: acc[i0+r][d0+..] += sum_e A[i][e] * B[e][d].
// A indexed [i][e] (reduction contiguous), stride astr. B indexed [e][d], stride bstr.
__device__ __forceinline__ void gemmC(const float* __restrict__ A, int astr,
                                      const float* __restrict__ Bm, int bstr,
                                      int red, int i0, int d0,
                                      unsigned long long acc[8][4]) {
    #pragma unroll 2
    for (int e = 0; e < red; e += 4) {
        ulonglong2 b[4][2];
        #pragma unroll
        for (int k = 0; k < 4; k++) {
            const float* br = Bm + (e + k) * bstr + d0;
            b[k][0] = *(const ulonglong2*)br;
            b[k][1] = *(const ulonglong2*)(br + 4);
        }
        #pragma unroll
        for (int r = 0; r < 8; r++) {
            float4 a4 = *(const float4*)(A + (i0 + r) * astr + e);
            unsigned long long a;
            a = bcast2(a4.x);
            ffma2(acc[r][0], a, b[0][0].x); ffma2(acc[r][1], a, b[0][0].y);
            ffma2(acc[r][2], a, b[0][1].x); ffma2(acc[r][3], a, b[0][1].y);
            a = bcast2(a4.y);
            ffma2(acc[r][0], a, b[1][0].x); ffma2(acc[r][1], a, b[1][0].y);
            ffma2(acc[r][2], a, b[1][1].x); ffma2(acc[r][3], a, b[1][1].y);
            a = bcast2(a4.z);
            ffma2(acc[r][0], a, b[2][0].x); ffma2(acc[r][1], a, b[2][0].y);
            ffma2(acc[r][2], a, b[2][1].x); ffma2(acc[r][3], a, b[2][1].y);
            a = bcast2(a4.w);
            ffma2(acc[r][0], a, b[3][0].x); ffma2(acc[r][1], a, b[3][0].y);
            ffma2(acc[r][2], a, b[3][1].x); ffma2(acc[r][3], a, b[3][1].y);
        }
    }
}

// GEMM variant R: acc[i0+r][d0+..] += sum_t A[t][i] * B[t][d]  (A-transpose GEMM).
__device__ __forceinline__ void gemmR(const float* __restrict__ A, int astr,
                                      const float* __restrict__ Bm, int bstr,
                                      int red, int i0, int d0,
                                      unsigned long long acc[8][4]) {
    #pragma unroll 4
    for (int t = 0; t < red; t++) {
        const float* br = Bm + t * bstr + d0;
        ulonglong2 b0 = *(const ulonglong2*)br;
        ulonglong2 b1 = *(const ulonglong2*)(br + 4);
        float4 alo = *(const float4*)(A + t * astr + i0);
        float4 ahi = *(const float4*)(A + t * astr + i0 + 4);
        float av[8] = {alo.x, alo.y, alo.z, alo.w, ahi.x, ahi.y, ahi.z, ahi.w};
        #pragma unroll
        for (int r = 0; r < 8; r++) {
            unsigned long long a = bcast2(av[r]);
            ffma2(acc[r][0], a, b0.x); ffma2(acc[r][1], a, b0.y);
            ffma2(acc[r][2], a, b1.x); ffma2(acc[r][3], a, b1.y);
        }
    }
}

__device__ __forceinline__ void store_acc8x8(float* dst, int dstr, int i0, int d0,
                                             unsigned long long acc[8][4]) {
    #pragma unroll
    for (int r = 0; r < 8; r++) {
        U2 u0, u1, u2, u3;
        u0.u = acc[r][0]; u1.u = acc[r][1]; u2.u = acc[r][2]; u3.u = acc[r][3];
        *(float4*)(dst + (i0 + r) * dstr + d0)     = make_float4(u0.f.x, u0.f.y, u1.f.x, u1.f.y);
        *(float4*)(dst + (i0 + r) * dstr + d0 + 4) = make_float4(u2.f.x, u2.f.y, u3.f.x, u3.f.y);
    }
}

// ---------------- Pass 0: trig table ---------------------------------------------------
__global__ void __launch_bounds__(256, 1)
trig_kernel() {
    int idx = blockIdx.x * 256 + threadIdx.x;      // 0 .. SS*64-1
    int t = idx >> 6, j = idx & 63;
    float invf = (float)exp(-((double)(2 * j) / 128.0) * log(10000.0));
    float ang = (float)t * invf;
    float sn, cs; sincos_safe(ang, &sn, &cs);
    g_trig[idx] = make_float2(cs, sn);
}

// ---------------- Pass 1: per-chunk KV state  S[e][d] = sum_t Kr[t][e] V[t][d] --------
__global__ void __launch_bounds__(256, 1)
kv_kernel(const float* __restrict__ K, const float* __restrict__ V) {
    extern __shared__ float sm[];
    float* sK = sm;                      // [128][QSTR]
    float* sV = sm + 128 * QSTR;         // [128][QSTR]
    int tid = threadIdx.x;
    int b = blockIdx.y, c = blockIdx.x;

    const float* gK = K + ((size_t)b * SS + (size_t)c * CC) * DD;
    const float* gV = V + ((size_t)b * SS + (size_t)c * CC) * DD;
    load_tile(sK, gK, 128, tid);
    load_tile(sV, gV, 128, tid);
    __syncthreads();
    rope_tile(sK, 128, c * CC, tid);
    __syncthreads();

    int tx = tid & 15, ty = tid >> 4;
    int e0 = ty * 8, d0 = tx * 8;
    unsigned long long acc[8][4];
    #pragma unroll
    for (int r = 0; r < 8; r++)
        #pragma unroll
        for (int p = 0; p < 4; p++) acc[r][p] = 0ull;

    gemmR(sK, QSTR, sV, QSTR, 128, e0, d0, acc);

    float* out = (float*)g_kv4 + ((size_t)(b * NC + c)) * DD * DD;
    store_acc8x8(out, DD, e0, d0, acc);
}

// ---------------- Pass 2: exclusive prefix over chunk states --------------------------
__global__ void __launch_bounds__(256, 1)
prefix_kernel() {
    int b = blockIdx.y;
    int idx4 = blockIdx.x * 256 + threadIdx.x;          // 0..4095 float4 per matrix
    const float4* kv = g_kv4  + (size_t)b * NC * 4096;
    float4*       pr = g_pre4 + (size_t)b * NC * 4096;
    float4 acc = make_float4(0.f, 0.f, 0.f, 0.f);
    #pragma unroll 8
    for (int c = 0; c < NC; c++) {
        pr[(size_t)c * 4096 + idx4] = acc;
        float4 v = kv[(size_t)c * 4096 + idx4];
        acc.x += v.x; acc.y += v.y; acc.z += v.z; acc.w += v.w;
    }
}

// ---------------- Pass 3: out = masked(Qr Kr^T) V + Qr @ M_prefix ---------------------
__global__ void __launch_bounds__(256, 1)
out_kernel(const float* __restrict__ Q, const float* __restrict__ K,
           const float* __restrict__ V, float* __restrict__ O) {
    extern __shared__ float sm[];
    float* sQ = sm;                       // [128][QSTR]
    float* sM = sQ + 128 * QSTR;          // [32][QSTR]
    float* sK = sM + 32 * QSTR;           // [32][QSTR]
    float* sV = sK + 32 * QSTR;           // [32][QSTR]
    float* sE = sV + 32 * QSTR;           // [128][ESTR]
    int tid = threadIdx.x;
    int b = blockIdx.y, c = blockIdx.x;

    load_tile(sQ, Q + ((size_t)b * SS + (size_t)c * CC) * DD, 128, tid);
    __syncthreads();
    rope_tile(sQ, 128, c * CC, tid);

    int tx = tid & 15, ty = tid >> 4;
    int i0 = ty * 8, d0 = tx * 8;
    unsigned long long acc[8][4];
    #pragma unroll
    for (int r = 0; r < 8; r++)
        #pragma unroll
        for (int p = 0; p < 4; p++) acc[r][p] = 0ull;

    // Stage A: acc += Qr @ M_prefix (stream 32 e-rows of M at a time).
    // Chunk 0 has an all-zero prefix state: skip (uniform branch per CTA).
    if (c > 0) {
        const float* gM = (const float*)g_pre4 + ((size_t)(b * NC + c)) * DD * DD;
        for (int mb = 0; mb < 4; mb++) {
            __syncthreads();                           // also orders rope(sQ) on mb==0
            load_tile(sM, gM + mb * 32 * DD, 32, tid);
            __syncthreads();
            gemmC(sQ + mb * 32, QSTR, sM, QSTR, 32, i0, d0, acc);
        }
    }

    // Stage B: intra-chunk causal attention, 32-key sub-blocks.
    // Triangular skip: for sub-block j, rows i < 32j are fully masked; skip
    // their E-compute and E@V. Both thread->row maps give warps contiguous
    // row spans vs 32-aligned thresholds, so the guards are warp-uniform.
    int tx4 = tid & 3, iy = tid >> 2;
    int ii0 = iy * 2;
    const float* gKc = K + ((size_t)b * SS + (size_t)c * CC) * DD;
    const float* gVc = V + ((size_t)b * SS + (size_t)c * CC) * DD;

    for (int j = 0; j < 4; j++) {
        int j32 = j * 32;
        __syncthreads();                               // prior sE/sV consumers done
        load_tile(sK, gKc + j * 32 * DD, 32, tid);     // (also orders rope(sQ) when c==0)
        load_tile(sV, gVc + j * 32 * DD, 32, tid);
        __syncthreads();
        rope_tile(sK, 32, c * CC + j32, tid);
        __syncthreads();

        // E[i][t] = Qr[i] . Kr[t], thread tile 2 rows x 8 keys, packed over d
        if (ii0 >= j32) {
            unsigned long long eacc[2][8];
            #pragma unroll
            for (int r = 0; r < 2; r++)
                #pragma unroll
                for (int u = 0; u < 8; u++) eacc[r][u] = 0ull;

            #pragma unroll 4
            for (int d4 = 0; d4 < 32; d4++) {
                ulonglong2 q0 = *(const ulonglong2*)(sQ + ii0 * QSTR + d4 * 4);
                ulonglong2 q1 = *(const ulonglong2*)(sQ + (ii0 + 1) * QSTR + d4 * 4);
                #pragma unroll
                for (int u = 0; u < 8; u++) {
                    ulonglong2 k2 = *(const ulonglong2*)(sK + (u * 4 + tx4) * QSTR + d4 * 4);
                    ffma2(eacc[0][u], q0.x, k2.x); ffma2(eacc[0][u], q0.y, k2.y);
                    ffma2(eacc[1][u], q1.x, k2.x); ffma2(eacc[1][u], q1.y, k2.y);
                }
            }
            #pragma unroll
            for (int r = 0; r < 2; r++) {
                int i = ii0 + r;
                #pragma unroll
                for (int u = 0; u < 8; u++) {
                    int t = u * 4 + tx4;
                    U2 v; v.u = eacc[r][u];
                    float e = v.f.x + v.f.y;             // horizontal add of d-parity
                    sE[i * ESTR + t] = (j32 + t <= i) ? e : 0.0f;   // causal mask
                }
            }
        }
        __syncthreads();
        if (i0 >= j32)
            gemmC(sE, ESTR, sV, QSTR, 32, i0, d0, acc);  // acc += E @ V
    }

    float* gO = O + ((size_t)b * SS + (size_t)c * CC) * DD;
    store_acc8x8(gO, DD, i0, d0, acc);
}

extern "C" void kernel_launch(void* const* d_in, const int* in_sizes, int n_in,
                              void* d_out, int out_size) {
    const float* Q = (const float*)d_in[0];
    const float* K = (const float*)d_in[1];
    const float* V = (const float*)d_in[2];
    float* O = (float*)d_out;

    int smem1 = 2 * 128 * QSTR * (int)sizeof(float);                       // 135168
    int smem3 = (128 * QSTR + 3 * 32 * QSTR + 128 * ESTR) * (int)sizeof(float); // 136704
    cudaFuncSetAttribute(kv_kernel,  cudaFuncAttributeMaxDynamicSharedMemorySize, smem1);
    cudaFuncSetAttribute(out_kernel, cudaFuncAttributeMaxDynamicSharedMemorySize, smem3);

    trig_kernel<<<SS * 64 / 256, 256>>>();
    kv_kernel<<<dim3(NC, BB), 256, smem1>>>(K, V);
    prefix_kernel<<<dim3(16, BB), 256>>>();
    out_kernel<<<dim3(NC, BB), 256, smem3>>>(Q, K, V, O);
}